// round 4
// baseline (speedup 1.0000x reference)
#include <cuda_runtime.h>
#include <math.h>

#define DD   2048
#define K3   6144
#define BB   4
#define TT   2048
#define MTOT 8192   // B*T

// Scratch: A = [g0*x | g1*integ | g2*deriv], row-major M x K3
__device__ float g_A[(size_t)MTOT * K3];

// ---------------------------------------------------------------------------
// Kernel 1: temporal scan. One thread per (b, d) channel.
//   s_t = a*s_{t-1} + (1-a)*x_t
//   d_t = be*d_{t-1} + (1-be)*(x_t - x_{t-1})
// Writes integ -> A[:, D:2D], deriv -> A[:, 2D:3D]
// ---------------------------------------------------------------------------
__global__ void scan_kernel(const float* __restrict__ x,
                            const float* __restrict__ alpha_logit,
                            const float* __restrict__ beta_logit) {
    int tid = blockIdx.x * blockDim.x + threadIdx.x;
    if (tid >= BB * DD) return;
    int d = tid & (DD - 1);
    int b = tid >> 11;

    float a  = 1.0f / (1.0f + expf(-alpha_logit[d]));
    float be = 1.0f / (1.0f + expf(-beta_logit[d]));
    float one_a  = 1.0f - a;
    float one_be = 1.0f - be;

    const float* xp = x + (size_t)b * TT * DD + d;
    float* Ai = g_A + (size_t)b * TT * K3 + DD + d;        // integral segment
    float* Ad = Ai + DD;                                    // derivative segment

    float s = 0.0f, dv = 0.0f, xprev = 0.0f;
    #pragma unroll 8
    for (int t = 0; t < TT; ++t) {
        float xt = xp[(size_t)t * DD];
        s  = a  * s  + one_a  * xt;
        dv = be * dv + one_be * (xt - xprev);
        xprev = xt;
        Ai[(size_t)t * K3] = s;
        Ad[(size_t)t * K3] = dv;
    }
}

// ---------------------------------------------------------------------------
// Kernel 2: per-row gate logits + softmax, then scale A segments in place and
// fill A[:, 0:D] = g0 * x. One block (256 threads) per row m.
// W_gate_w layout: (3, 3*D) row-major; k = [x | integ | deriv].
// ---------------------------------------------------------------------------
__global__ void gate_kernel(const float* __restrict__ x,
                            const float* __restrict__ Wg,
                            const float* __restrict__ Wgb) {
    int m   = blockIdx.x;
    int tid = threadIdx.x;
    const float* xr = x + (size_t)m * DD;
    float* Ar = g_A + (size_t)m * K3;

    float a0 = 0.f, a1 = 0.f, a2 = 0.f;
    for (int d = tid; d < DD; d += 256) {
        float xv = xr[d];
        float iv = Ar[DD + d];
        float dv = Ar[2 * DD + d];
        a0 += xv * Wg[d]            + iv * Wg[DD + d]            + dv * Wg[2*DD + d];
        a1 += xv * Wg[K3 + d]       + iv * Wg[K3 + DD + d]       + dv * Wg[K3 + 2*DD + d];
        a2 += xv * Wg[2*K3 + d]     + iv * Wg[2*K3 + DD + d]     + dv * Wg[2*K3 + 2*DD + d];
    }

    __shared__ float r0[256], r1[256], r2[256];
    r0[tid] = a0; r1[tid] = a1; r2[tid] = a2;
    __syncthreads();
    for (int s = 128; s > 0; s >>= 1) {
        if (tid < s) {
            r0[tid] += r0[tid + s];
            r1[tid] += r1[tid + s];
            r2[tid] += r2[tid + s];
        }
        __syncthreads();
    }

    __shared__ float gsm[3];
    if (tid == 0) {
        float l0 = r0[0] + Wgb[0];
        float l1 = r1[0] + Wgb[1];
        float l2 = r2[0] + Wgb[2];
        float mx = fmaxf(l0, fmaxf(l1, l2));
        float e0 = expf(l0 - mx), e1 = expf(l1 - mx), e2 = expf(l2 - mx);
        float inv = 1.0f / (e0 + e1 + e2);
        gsm[0] = e0 * inv; gsm[1] = e1 * inv; gsm[2] = e2 * inv;
    }
    __syncthreads();
    float g0 = gsm[0], g1 = gsm[1], g2 = gsm[2];

    for (int d = tid; d < DD; d += 256) {
        Ar[d]           = g0 * xr[d];
        Ar[DD + d]     *= g1;
        Ar[2 * DD + d] *= g2;
    }
}

// ---------------------------------------------------------------------------
// Kernel 3: SGEMM  y[m, o] = sum_k A[m, k] * Wcat[o, k] + bias[o]
// Wcat[o, :] = [W_p[o,:] | W_i[o,:] | W_d[o,:]]   (TN GEMM, K = 6144)
// 128x128 block tile, BK=8, 8x8 per thread, 256 threads.
// ---------------------------------------------------------------------------
#define BM 128
#define BN 128
#define BK 8

__global__ __launch_bounds__(256, 2)
void gemm_kernel(const float* __restrict__ Wp,
                 const float* __restrict__ Wi,
                 const float* __restrict__ Wd,
                 const float* __restrict__ bias,
                 float* __restrict__ y) {
    __shared__ float As[BK][BM];
    __shared__ float Bs[BK][BN];

    int tid = threadIdx.x;
    int m0 = blockIdx.y * BM;
    int n0 = blockIdx.x * BN;
    int tx = tid & 15;        // 0..15 -> n sub-tile
    int ty = tid >> 4;        // 0..15 -> m sub-tile
    int lrow = tid >> 1;      // 0..127 (row within tile for loads)
    int lk   = (tid & 1) * 4; // 0 or 4 (k-quad within BK)

    const float* Wt[3] = {Wp, Wi, Wd};

    float acc[8][8];
    #pragma unroll
    for (int i = 0; i < 8; ++i)
        #pragma unroll
        for (int j = 0; j < 8; ++j) acc[i][j] = 0.0f;

    for (int k0 = 0; k0 < K3; k0 += BK) {
        const float* Wb = Wt[k0 >> 11];
        int kk0 = k0 & (DD - 1);

        float4 av = *(const float4*)(g_A + (size_t)(m0 + lrow) * K3 + k0 + lk);
        float4 bv = *(const float4*)(Wb  + (size_t)(n0 + lrow) * DD + kk0 + lk);
        As[lk + 0][lrow] = av.x; As[lk + 1][lrow] = av.y;
        As[lk + 2][lrow] = av.z; As[lk + 3][lrow] = av.w;
        Bs[lk + 0][lrow] = bv.x; Bs[lk + 1][lrow] = bv.y;
        Bs[lk + 2][lrow] = bv.z; Bs[lk + 3][lrow] = bv.w;
        __syncthreads();

        #pragma unroll
        for (int kk = 0; kk < BK; ++kk) {
            float a[8], b[8];
            #pragma unroll
            for (int i = 0; i < 8; ++i) a[i] = As[kk][ty * 8 + i];
            #pragma unroll
            for (int j = 0; j < 8; ++j) b[j] = Bs[kk][tx * 8 + j];
            #pragma unroll
            for (int i = 0; i < 8; ++i)
                #pragma unroll
                for (int j = 0; j < 8; ++j)
                    acc[i][j] += a[i] * b[j];
        }
        __syncthreads();
    }

    // Epilogue: + bias, vectorized float4 stores
    #pragma unroll
    for (int i = 0; i < 8; ++i) {
        int m = m0 + ty * 8 + i;
        float* yr = y + (size_t)m * DD + n0 + tx * 8;
        #pragma unroll
        for (int j = 0; j < 8; j += 4) {
            int n = n0 + tx * 8 + j;
            float4 v;
            v.x = acc[i][j + 0] + bias[n + 0];
            v.y = acc[i][j + 1] + bias[n + 1];
            v.z = acc[i][j + 2] + bias[n + 2];
            v.w = acc[i][j + 3] + bias[n + 3];
            *(float4*)(yr + j) = v;
        }
    }
}

// ---------------------------------------------------------------------------
// Launch
// ---------------------------------------------------------------------------
extern "C" void kernel_launch(void* const* d_in, const int* in_sizes, int n_in,
                              void* d_out, int out_size) {
    const float* x      = (const float*)d_in[0];  // (4,2048,2048)
    const float* W_p    = (const float*)d_in[1];  // (2048,2048)
    const float* W_i    = (const float*)d_in[2];
    const float* W_d    = (const float*)d_in[3];
    const float* a_log  = (const float*)d_in[4];  // (2048,)
    const float* b_log  = (const float*)d_in[5];  // (2048,)
    const float* W_gw   = (const float*)d_in[6];  // (3,6144)
    const float* W_gb   = (const float*)d_in[7];  // (3,)
    const float* bias   = (const float*)d_in[8];  // (2048,)
    float* y = (float*)d_out;                     // (4,2048,2048)

    // 1) temporal scan: 8192 channels
    scan_kernel<<<(BB * DD + 255) / 256, 256>>>(x, a_log, b_log);

    // 2) gates + in-place scaling of A
    gate_kernel<<<MTOT, 256>>>(x, W_gw, W_gb);

    // 3) fused GEMM + bias
    dim3 grid(DD / BN, MTOT / BM);   // (16, 64)
    gemm_kernel<<<grid, 256>>>(W_p, W_i, W_d, bias, y);
}

// round 7
// speedup vs baseline: 1.6825x; 1.6825x over previous
#include <cuda_runtime.h>
#include <cuda_bf16.h>
#include <math.h>
#include <stdint.h>

#define DD   2048
#define K3   6144
#define BB   4
#define TT   2048
#define MTOT 8192   // B*T

// ---------------- scratch (device globals; no allocation) -------------------
__device__ float g_I [(size_t)MTOT * DD];             // integral  (fp32)
__device__ float g_Dv[(size_t)MTOT * DD];             // derivative(fp32)
__device__ __nv_bfloat16 g_Ahi[(size_t)MTOT * K3];    // gated features hi
__device__ __nv_bfloat16 g_Alo[(size_t)MTOT * K3];    // gated features lo
__device__ __nv_bfloat16 g_Whi[(size_t)DD * K3];      // [Wp|Wi|Wd] hi
__device__ __nv_bfloat16 g_Wlo[(size_t)DD * K3];      // [Wp|Wi|Wd] lo

// ---------------- helpers ----------------------------------------------------
__device__ __forceinline__ uint32_t smem_u32(const void* p) {
    uint32_t a;
    asm("{ .reg .u64 t; cvta.to.shared.u64 t, %1; cvt.u32.u64 %0, t; }"
        : "=r"(a) : "l"(p));
    return a;
}
__device__ __forceinline__ void cp16(uint32_t dst, const void* src) {
    asm volatile("cp.async.cg.shared.global [%0], [%1], 16;\n"
                 :: "r"(dst), "l"(src));
}
#define CP_COMMIT()  asm volatile("cp.async.commit_group;\n" ::: "memory")
#define CP_WAIT(n)   asm volatile("cp.async.wait_group %0;\n" :: "n"(n) : "memory")

__device__ __forceinline__ void ldm_x4(uint32_t& r0, uint32_t& r1,
                                       uint32_t& r2, uint32_t& r3, uint32_t addr) {
    asm volatile("ldmatrix.sync.aligned.m8n8.x4.shared.b16 {%0,%1,%2,%3}, [%4];"
                 : "=r"(r0), "=r"(r1), "=r"(r2), "=r"(r3) : "r"(addr));
}
__device__ __forceinline__ void mma_bf16(float* c, const uint32_t* a,
                                         uint32_t b0, uint32_t b1) {
    asm volatile(
        "mma.sync.aligned.m16n8k16.row.col.f32.bf16.bf16.f32 "
        "{%0,%1,%2,%3}, {%4,%5,%6,%7}, {%8,%9}, {%0,%1,%2,%3};"
        : "+f"(c[0]), "+f"(c[1]), "+f"(c[2]), "+f"(c[3])
        : "r"(a[0]), "r"(a[1]), "r"(a[2]), "r"(a[3]), "r"(b0), "r"(b1));
}

__device__ __forceinline__ void split_bf16(float v, __nv_bfloat16& hi, __nv_bfloat16& lo) {
    hi = __float2bfloat16(v);
    lo = __float2bfloat16(v - __bfloat162float(hi));
}

// ---------------------------------------------------------------------------
// Kernel 1: temporal scan. One thread per (b, d) channel; 64-thread blocks so
// 8192 threads spread over 128 blocks (R4 ncu: occ 12.4% with 32 blocks).
// ---------------------------------------------------------------------------
__global__ void scan_kernel(const float* __restrict__ x,
                            const float* __restrict__ alpha_logit,
                            const float* __restrict__ beta_logit) {
    int tid = blockIdx.x * blockDim.x + threadIdx.x;
    if (tid >= BB * DD) return;
    int d = tid & (DD - 1);
    int b = tid >> 11;

    float a  = 1.0f / (1.0f + expf(-alpha_logit[d]));
    float be = 1.0f / (1.0f + expf(-beta_logit[d]));
    float one_a  = 1.0f - a;
    float one_be = 1.0f - be;

    const float* xp = x    + (size_t)b * TT * DD + d;
    float* Ip = g_I  + (size_t)b * TT * DD + d;
    float* Dp = g_Dv + (size_t)b * TT * DD + d;

    float s = 0.0f, dv = 0.0f, xprev = 0.0f;
    #pragma unroll 8
    for (int t = 0; t < TT; ++t) {
        float xt = xp[(size_t)t * DD];
        s  = a  * s  + one_a  * xt;
        dv = be * dv + one_be * (xt - xprev);
        xprev = xt;
        Ip[(size_t)t * DD] = s;
        Dp[(size_t)t * DD] = dv;
    }
}

// ---------------------------------------------------------------------------
// Kernel 2: W -> concatenated bf16 hi/lo: W'[o, 0:2048|2048:4096|4096:6144]
// ---------------------------------------------------------------------------
__global__ void wconv_kernel(const float* __restrict__ Wp,
                             const float* __restrict__ Wi,
                             const float* __restrict__ Wd) {
    size_t i4 = (size_t)blockIdx.x * blockDim.x + threadIdx.x;
    if (i4 >= (size_t)DD * K3 / 4) return;
    size_t idx = i4 * 4;
    int o = (int)(idx / K3);
    int k = (int)(idx % K3);
    const float* src = (k < DD)     ? Wp + (size_t)o * DD + k
                     : (k < 2 * DD) ? Wi + (size_t)o * DD + (k - DD)
                                    : Wd + (size_t)o * DD + (k - 2 * DD);
    float4 v = *(const float4*)src;
    __nv_bfloat16 h0, l0, h1, l1, h2, l2, h3, l3;
    split_bf16(v.x, h0, l0); split_bf16(v.y, h1, l1);
    split_bf16(v.z, h2, l2); split_bf16(v.w, h3, l3);
    __nv_bfloat162* hp = (__nv_bfloat162*)(g_Whi + idx);
    __nv_bfloat162* lp = (__nv_bfloat162*)(g_Wlo + idx);
    hp[0] = __nv_bfloat162(h0, h1); hp[1] = __nv_bfloat162(h2, h3);
    lp[0] = __nv_bfloat162(l0, l1); lp[1] = __nv_bfloat162(l2, l3);
}

// ---------------------------------------------------------------------------
// Kernel 3: gates (fp32 softmax) + emit scaled bf16 hi/lo A = [g0*x|g1*I|g2*D]
// ---------------------------------------------------------------------------
__global__ void gate_kernel(const float* __restrict__ x,
                            const float* __restrict__ Wg,
                            const float* __restrict__ Wgb) {
    int m   = blockIdx.x;
    int tid = threadIdx.x;
    const float* xr = x    + (size_t)m * DD;
    const float* Ir = g_I  + (size_t)m * DD;
    const float* Dr = g_Dv + (size_t)m * DD;

    float a0 = 0.f, a1 = 0.f, a2 = 0.f;
    for (int d = tid; d < DD; d += 256) {
        float xv = xr[d], iv = Ir[d], dv = Dr[d];
        a0 += xv * Wg[d]        + iv * Wg[DD + d]        + dv * Wg[2*DD + d];
        a1 += xv * Wg[K3 + d]   + iv * Wg[K3 + DD + d]   + dv * Wg[K3 + 2*DD + d];
        a2 += xv * Wg[2*K3 + d] + iv * Wg[2*K3 + DD + d] + dv * Wg[2*K3 + 2*DD + d];
    }

    __shared__ float r0[256], r1[256], r2[256];
    r0[tid] = a0; r1[tid] = a1; r2[tid] = a2;
    __syncthreads();
    for (int s = 128; s > 0; s >>= 1) {
        if (tid < s) { r0[tid] += r0[tid+s]; r1[tid] += r1[tid+s]; r2[tid] += r2[tid+s]; }
        __syncthreads();
    }

    __shared__ float gsm[3];
    if (tid == 0) {
        float l0 = r0[0] + Wgb[0], l1 = r1[0] + Wgb[1], l2 = r2[0] + Wgb[2];
        float mx = fmaxf(l0, fmaxf(l1, l2));
        float e0 = expf(l0 - mx), e1 = expf(l1 - mx), e2 = expf(l2 - mx);
        float inv = 1.0f / (e0 + e1 + e2);
        gsm[0] = e0 * inv; gsm[1] = e1 * inv; gsm[2] = e2 * inv;
    }
    __syncthreads();
    float g0 = gsm[0], g1 = gsm[1], g2 = gsm[2];

    __nv_bfloat16* Ah = g_Ahi + (size_t)m * K3;
    __nv_bfloat16* Al = g_Alo + (size_t)m * K3;
    for (int d = tid; d < DD; d += 256) {
        __nv_bfloat16 h, l;
        split_bf16(g0 * xr[d], h, l);  Ah[d]        = h;  Al[d]        = l;
        split_bf16(g1 * Ir[d], h, l);  Ah[DD + d]   = h;  Al[DD + d]   = l;
        split_bf16(g2 * Dr[d], h, l);  Ah[2*DD + d] = h;  Al[2*DD + d] = l;
    }
}

// ---------------------------------------------------------------------------
// Kernel 4: mma.sync bf16 GEMM, 3-term split:
//   y = Ahi*Whi^T + Ahi*Wlo^T + Alo*Whi^T + bias      (lo*lo dropped, ~2^-18)
// Block tile 128(m) x 256(n), BK=32, 8 warps (2x4), warp tile 64x64.
// 4-stage cp.async pipeline; smem rows padded to 80B (conflict-free ldmatrix).
// ---------------------------------------------------------------------------
#define NSUB_STEPS 192          // K3 / 32
#define NSTEP (3 * NSUB_STEPS)  // 576
#define ROWSTRIDE 80
#define A_STAGE_BYTES (128 * ROWSTRIDE)   // 10240
#define B_STAGE_BYTES (256 * ROWSTRIDE)   // 20480
#define STAGE_BYTES (A_STAGE_BYTES + B_STAGE_BYTES)  // 30720
#define NSTAGE 4
#define GEMM_SMEM (NSTAGE * STAGE_BYTES)  // 122880

__device__ __forceinline__ void issue_stage(uint32_t sbase, int s_idx, int stage,
                                            int m0, int n0, int tid) {
    int sub = (s_idx >= 2 * NSUB_STEPS) ? 2 : (s_idx >= NSUB_STEPS ? 1 : 0);
    int k0  = (s_idx - sub * NSUB_STEPS) * 32;
    const __nv_bfloat16* Asrc = (sub < 2)  ? g_Ahi : g_Alo;
    const __nv_bfloat16* Bsrc = (sub == 1) ? g_Wlo : g_Whi;
    uint32_t sA = sbase + stage * STAGE_BYTES;
    uint32_t sB = sA + A_STAGE_BYTES;

    // A tile: 128 rows x 64B -> 512 cp16 (2 per thread)
    #pragma unroll
    for (int q = 0; q < 2; ++q) {
        int idx = tid * 2 + q;
        int row = idx >> 2, c = idx & 3;
        const char* src = (const char*)Asrc
                        + (((size_t)(m0 + row) * K3 + k0) << 1) + c * 16;
        cp16(sA + row * ROWSTRIDE + c * 16, src);
    }
    // B tile: 256 rows x 64B -> 1024 cp16 (row = tid, 4 chunks)
    {
        const char* src = (const char*)Bsrc + (((size_t)(n0 + tid) * K3 + k0) << 1);
        uint32_t d = sB + tid * ROWSTRIDE;
        #pragma unroll
        for (int c = 0; c < 4; ++c) cp16(d + c * 16, src + c * 16);
    }
    CP_COMMIT();
}

__global__ __launch_bounds__(256, 1)
void gemm_kernel(const float* __restrict__ bias, float* __restrict__ y) {
    extern __shared__ char smem[];
    uint32_t sbase = smem_u32(smem);
    const int tid  = threadIdx.x;
    const int wid  = tid >> 5;
    const int lane = tid & 31;
    const int n0 = blockIdx.x * 256;
    const int m0 = blockIdx.y * 128;

    const int warp_m = wid & 1;          // 0..1 -> m offset 0/64
    const int warp_n = wid >> 1;         // 0..3 -> n offset 0/64/128/192
    const int m_base = warp_m * 64;
    const int n_base = warp_n * 64;

    // ldmatrix per-thread address pattern: row = base + (lane&15), chunk = lane>>4
    const uint32_t frag_off = (lane & 15) * ROWSTRIDE + (lane >> 4) * 16;

    float acc[4][8][4];
    #pragma unroll
    for (int i = 0; i < 4; ++i)
        #pragma unroll
        for (int j = 0; j < 8; ++j)
            #pragma unroll
            for (int q = 0; q < 4; ++q) acc[i][j][q] = 0.0f;

    // prologue: fill stages 0..2
    issue_stage(sbase, 0, 0, m0, n0, tid);
    issue_stage(sbase, 1, 1, m0, n0, tid);
    issue_stage(sbase, 2, 2, m0, n0, tid);

    for (int i = 0; i < NSTEP; ++i) {
        if (i < NSTEP - 2)      CP_WAIT(2);
        else if (i == NSTEP - 2) CP_WAIT(1);
        else                     CP_WAIT(0);
        __syncthreads();

        if (i + 3 < NSTEP) issue_stage(sbase, i + 3, (i + 3) & 3, m0, n0, tid);

        uint32_t sA = sbase + (i & 3) * STAGE_BYTES;
        uint32_t sB = sA + A_STAGE_BYTES;
        uint32_t aA = sA + m_base * ROWSTRIDE + frag_off;
        uint32_t aB = sB + n_base * ROWSTRIDE + frag_off;

        #pragma unroll
        for (int kk = 0; kk < 2; ++kk) {
            uint32_t a[4][4], b[4][4];
            #pragma unroll
            for (int mt = 0; mt < 4; ++mt)
                ldm_x4(a[mt][0], a[mt][1], a[mt][2], a[mt][3],
                       aA + mt * (16 * ROWSTRIDE) + kk * 32);
            #pragma unroll
            for (int nt = 0; nt < 4; ++nt)
                ldm_x4(b[nt][0], b[nt][1], b[nt][2], b[nt][3],
                       aB + nt * (16 * ROWSTRIDE) + kk * 32);
            // non-trans ldmatrix on n-major B: regs {r0,r2} = n0-7 operand,
            // {r1,r3} = n8-15 operand (matches m16n8k16 .col B layout)
            #pragma unroll
            for (int mt = 0; mt < 4; ++mt)
                #pragma unroll
                for (int nt = 0; nt < 4; ++nt) {
                    mma_bf16(acc[mt][2 * nt + 0], a[mt], b[nt][0], b[nt][2]);
                    mma_bf16(acc[mt][2 * nt + 1], a[mt], b[nt][1], b[nt][3]);
                }
        }
    }

    // epilogue: c frag mapping -> y + bias
    const int g  = lane >> 2;
    const int tg = lane & 3;
    #pragma unroll
    for (int mt = 0; mt < 4; ++mt) {
        int m = m0 + m_base + mt * 16 + g;
        #pragma unroll
        for (int nt = 0; nt < 8; ++nt) {
            int n = n0 + n_base + nt * 8 + tg * 2;
            float b0 = bias[n], b1 = bias[n + 1];
            float2 v0 = make_float2(acc[mt][nt][0] + b0, acc[mt][nt][1] + b1);
            float2 v1 = make_float2(acc[mt][nt][2] + b0, acc[mt][nt][3] + b1);
            *(float2*)(y + (size_t)m * DD + n)       = v0;
            *(float2*)(y + (size_t)(m + 8) * DD + n) = v1;
        }
    }
}

// ---------------------------------------------------------------------------
// Launch
// ---------------------------------------------------------------------------
extern "C" void kernel_launch(void* const* d_in, const int* in_sizes, int n_in,
                              void* d_out, int out_size) {
    const float* x     = (const float*)d_in[0];
    const float* W_p   = (const float*)d_in[1];
    const float* W_i   = (const float*)d_in[2];
    const float* W_d   = (const float*)d_in[3];
    const float* a_log = (const float*)d_in[4];
    const float* b_log = (const float*)d_in[5];
    const float* W_gw  = (const float*)d_in[6];
    const float* W_gb  = (const float*)d_in[7];
    const float* bias  = (const float*)d_in[8];
    float* y = (float*)d_out;

    static int smem_set = 0;
    if (!smem_set) {
        cudaFuncSetAttribute(gemm_kernel,
                             cudaFuncAttributeMaxDynamicSharedMemorySize, GEMM_SMEM);
        smem_set = 1;
    }

    // 1) weight conversion (independent of scan/gate)
    {
        int n4 = DD * K3 / 4;
        wconv_kernel<<<(n4 + 255) / 256, 256>>>(W_p, W_i, W_d);
    }
    // 2) temporal scan
    scan_kernel<<<(BB * DD + 63) / 64, 64>>>(x, a_log, b_log);
    // 3) gates + split-bf16 feature emit
    gate_kernel<<<MTOT, 256>>>(x, W_gw, W_gb);
    // 4) tensor-core GEMM + bias
    dim3 grid(DD / 256, MTOT / 128);   // (8, 64)
    gemm_kernel<<<grid, 256, GEMM_SMEM>>>(bias, y);
}

// round 10
// speedup vs baseline: 2.4488x; 1.4554x over previous
#include <cuda_runtime.h>
#include <cuda_bf16.h>
#include <math.h>
#include <stdint.h>

#define DD   2048
#define K3   6144
#define BB   4
#define TT   2048
#define MTOT 8192   // B*T

// ---------------- scratch (device globals; no allocation) -------------------
__device__ float g_I [(size_t)MTOT * DD];             // integral  (fp32)
__device__ float g_Dv[(size_t)MTOT * DD];             // derivative(fp32)
__device__ __nv_bfloat16 g_Ahi[(size_t)MTOT * K3];    // gated features hi
__device__ __nv_bfloat16 g_Alo[(size_t)MTOT * K3];    // gated features lo
__device__ __nv_bfloat16 g_Whi[(size_t)DD * K3];      // [Wp|Wi|Wd] hi
__device__ __nv_bfloat16 g_Wlo[(size_t)DD * K3];      // [Wp|Wi|Wd] lo

// ---------------- helpers ----------------------------------------------------
__device__ __forceinline__ uint32_t smem_u32(const void* p) {
    uint32_t a;
    asm("{ .reg .u64 t; cvta.to.shared.u64 t, %1; cvt.u32.u64 %0, t; }"
        : "=r"(a) : "l"(p));
    return a;
}
__device__ __forceinline__ void cp16(uint32_t dst, const void* src) {
    asm volatile("cp.async.cg.shared.global [%0], [%1], 16;\n"
                 :: "r"(dst), "l"(src));
}
#define CP_COMMIT()  asm volatile("cp.async.commit_group;\n" ::: "memory")
#define CP_WAIT(n)   asm volatile("cp.async.wait_group %0;\n" :: "n"(n) : "memory")

__device__ __forceinline__ void ldm_x4(uint32_t& r0, uint32_t& r1,
                                       uint32_t& r2, uint32_t& r3, uint32_t addr) {
    asm volatile("ldmatrix.sync.aligned.m8n8.x4.shared.b16 {%0,%1,%2,%3}, [%4];"
                 : "=r"(r0), "=r"(r1), "=r"(r2), "=r"(r3) : "r"(addr));
}
__device__ __forceinline__ void mma_bf16(float* c, const uint32_t* a,
                                         uint32_t b0, uint32_t b1) {
    asm volatile(
        "mma.sync.aligned.m16n8k16.row.col.f32.bf16.bf16.f32 "
        "{%0,%1,%2,%3}, {%4,%5,%6,%7}, {%8,%9}, {%0,%1,%2,%3};"
        : "+f"(c[0]), "+f"(c[1]), "+f"(c[2]), "+f"(c[3])
        : "r"(a[0]), "r"(a[1]), "r"(a[2]), "r"(a[3]), "r"(b0), "r"(b1));
}

__device__ __forceinline__ void split_bf16(float v, __nv_bfloat16& hi, __nv_bfloat16& lo) {
    hi = __float2bfloat16(v);
    lo = __float2bfloat16(v - __bfloat162float(hi));
}

// ---------------------------------------------------------------------------
// Kernel 1: temporal scan. One thread per (b, d) channel.
// ---------------------------------------------------------------------------
__global__ void scan_kernel(const float* __restrict__ x,
                            const float* __restrict__ alpha_logit,
                            const float* __restrict__ beta_logit) {
    int tid = blockIdx.x * blockDim.x + threadIdx.x;
    if (tid >= BB * DD) return;
    int d = tid & (DD - 1);
    int b = tid >> 11;

    float a  = 1.0f / (1.0f + expf(-alpha_logit[d]));
    float be = 1.0f / (1.0f + expf(-beta_logit[d]));
    float one_a  = 1.0f - a;
    float one_be = 1.0f - be;

    const float* xp = x    + (size_t)b * TT * DD + d;
    float* Ip = g_I  + (size_t)b * TT * DD + d;
    float* Dp = g_Dv + (size_t)b * TT * DD + d;

    float s = 0.0f, dv = 0.0f, xprev = 0.0f;
    #pragma unroll 8
    for (int t = 0; t < TT; ++t) {
        float xt = xp[(size_t)t * DD];
        s  = a  * s  + one_a  * xt;
        dv = be * dv + one_be * (xt - xprev);
        xprev = xt;
        Ip[(size_t)t * DD] = s;
        Dp[(size_t)t * DD] = dv;
    }
}

// ---------------------------------------------------------------------------
// Kernel 2: W -> concatenated bf16 hi/lo: W'[o, 0:2048|2048:4096|4096:6144]
// ---------------------------------------------------------------------------
__global__ void wconv_kernel(const float* __restrict__ Wp,
                             const float* __restrict__ Wi,
                             const float* __restrict__ Wd) {
    size_t i4 = (size_t)blockIdx.x * blockDim.x + threadIdx.x;
    if (i4 >= (size_t)DD * K3 / 4) return;
    size_t idx = i4 * 4;
    int o = (int)(idx / K3);
    int k = (int)(idx % K3);
    const float* src = (k < DD)     ? Wp + (size_t)o * DD + k
                     : (k < 2 * DD) ? Wi + (size_t)o * DD + (k - DD)
                                    : Wd + (size_t)o * DD + (k - 2 * DD);
    float4 v = *(const float4*)src;
    __nv_bfloat16 h0, l0, h1, l1, h2, l2, h3, l3;
    split_bf16(v.x, h0, l0); split_bf16(v.y, h1, l1);
    split_bf16(v.z, h2, l2); split_bf16(v.w, h3, l3);
    __nv_bfloat162* hp = (__nv_bfloat162*)(g_Whi + idx);
    __nv_bfloat162* lp = (__nv_bfloat162*)(g_Wlo + idx);
    hp[0] = __nv_bfloat162(h0, h1); hp[1] = __nv_bfloat162(h2, h3);
    lp[0] = __nv_bfloat162(l0, l1); lp[1] = __nv_bfloat162(l2, l3);
}

// ---------------------------------------------------------------------------
// Kernel 3: gates (fp32 softmax) + emit scaled bf16 hi/lo A = [g0*x|g1*I|g2*D]
// ---------------------------------------------------------------------------
__global__ void gate_kernel(const float* __restrict__ x,
                            const float* __restrict__ Wg,
                            const float* __restrict__ Wgb) {
    int m   = blockIdx.x;
    int tid = threadIdx.x;
    const float* xr = x    + (size_t)m * DD;
    const float* Ir = g_I  + (size_t)m * DD;
    const float* Dr = g_Dv + (size_t)m * DD;

    float a0 = 0.f, a1 = 0.f, a2 = 0.f;
    for (int d = tid; d < DD; d += 256) {
        float xv = xr[d], iv = Ir[d], dv = Dr[d];
        a0 += xv * Wg[d]        + iv * Wg[DD + d]        + dv * Wg[2*DD + d];
        a1 += xv * Wg[K3 + d]   + iv * Wg[K3 + DD + d]   + dv * Wg[K3 + 2*DD + d];
        a2 += xv * Wg[2*K3 + d] + iv * Wg[2*K3 + DD + d] + dv * Wg[2*K3 + 2*DD + d];
    }

    __shared__ float r0[256], r1[256], r2[256];
    r0[tid] = a0; r1[tid] = a1; r2[tid] = a2;
    __syncthreads();
    for (int s = 128; s > 0; s >>= 1) {
        if (tid < s) { r0[tid] += r0[tid+s]; r1[tid] += r1[tid+s]; r2[tid] += r2[tid+s]; }
        __syncthreads();
    }

    __shared__ float gsm[3];
    if (tid == 0) {
        float l0 = r0[0] + Wgb[0], l1 = r1[0] + Wgb[1], l2 = r2[0] + Wgb[2];
        float mx = fmaxf(l0, fmaxf(l1, l2));
        float e0 = expf(l0 - mx), e1 = expf(l1 - mx), e2 = expf(l2 - mx);
        float inv = 1.0f / (e0 + e1 + e2);
        gsm[0] = e0 * inv; gsm[1] = e1 * inv; gsm[2] = e2 * inv;
    }
    __syncthreads();
    float g0 = gsm[0], g1 = gsm[1], g2 = gsm[2];

    __nv_bfloat16* Ah = g_Ahi + (size_t)m * K3;
    __nv_bfloat16* Al = g_Alo + (size_t)m * K3;
    for (int d = tid; d < DD; d += 256) {
        __nv_bfloat16 h, l;
        split_bf16(g0 * xr[d], h, l);  Ah[d]        = h;  Al[d]        = l;
        split_bf16(g1 * Ir[d], h, l);  Ah[DD + d]   = h;  Al[DD + d]   = l;
        split_bf16(g2 * Dr[d], h, l);  Ah[2*DD + d] = h;  Al[2*DD + d] = l;
    }
}

// ---------------------------------------------------------------------------
// Kernel 4: mma.sync bf16 GEMM, FUSED 3-term split per K-step:
//   y = Ahi*Whi^T + Ahi*Wlo^T + Alo*Whi^T + bias      (lo*lo dropped, ~2^-18)
// Block 128(m) x 256(n), BK=32 per stage carrying {Ahi,Alo,Whi,Wlo}.
// 512 threads = 16 warps (4m x 4n), warp tile 32x64.
// 3-stage cp.async pipeline (61.4KB/stage); 1 barrier per K-step (192 total).
// ---------------------------------------------------------------------------
#define NKSTEP 192              // K3 / 32
#define ROWSTRIDE 80
#define AH_OFF 0
#define AL_OFF 10240            // 128*80
#define BH_OFF 20480
#define BL_OFF 40960            // BH + 256*80
#define STAGE_BYTES 61440
#define NSTAGE 3
#define GEMM_SMEM (NSTAGE * STAGE_BYTES)   // 184320

__device__ __forceinline__ void issue_stage(uint32_t sbase, int kstep, int slot,
                                            int m0, int n0, int tid) {
    const int k0 = kstep * 32;
    uint32_t sS = sbase + slot * STAGE_BYTES;

    // A tiles (hi+lo): 128 rows x 4 chunks each -> 512 ops/buf, 1 per thread
    {
        int row = tid >> 2, c = tid & 3;
        size_t go = (((size_t)(m0 + row) * K3 + k0) << 1) + c * 16;
        uint32_t so = row * ROWSTRIDE + c * 16;
        cp16(sS + AH_OFF + so, (const char*)g_Ahi + go);
        cp16(sS + AL_OFF + so, (const char*)g_Alo + go);
    }
    // B tiles (hi+lo): 256 rows x 4 chunks each -> 1024 ops/buf, 2 per thread
    #pragma unroll
    for (int q = 0; q < 2; ++q) {
        int idx = tid + q * 512;
        int row = idx >> 2, c = idx & 3;
        size_t go = (((size_t)(n0 + row) * K3 + k0) << 1) + c * 16;
        uint32_t so = row * ROWSTRIDE + c * 16;
        cp16(sS + BH_OFF + so, (const char*)g_Whi + go);
        cp16(sS + BL_OFF + so, (const char*)g_Wlo + go);
    }
    CP_COMMIT();
}

__global__ __launch_bounds__(512, 1)
void gemm_kernel(const float* __restrict__ bias, float* __restrict__ y) {
    extern __shared__ char smem[];
    uint32_t sbase = smem_u32(smem);
    const int tid  = threadIdx.x;
    const int wid  = tid >> 5;
    const int lane = tid & 31;
    const int n0 = blockIdx.x * 256;
    const int m0 = blockIdx.y * 128;

    const int m_base = (wid & 3) * 32;    // 4 warps along m
    const int n_base = (wid >> 2) * 64;   // 4 warps along n

    // ldmatrix per-thread pattern: row = base + (lane&15), chunk = lane>>4
    const uint32_t frag_off = (lane & 15) * ROWSTRIDE + (lane >> 4) * 16;

    float acc[2][8][4];
    #pragma unroll
    for (int i = 0; i < 2; ++i)
        #pragma unroll
        for (int j = 0; j < 8; ++j)
            #pragma unroll
            for (int q = 0; q < 4; ++q) acc[i][j][q] = 0.0f;

    // prologue: fill stages 0, 1
    issue_stage(sbase, 0, 0, m0, n0, tid);
    issue_stage(sbase, 1, 1, m0, n0, tid);

    int slot = 0;
    for (int i = 0; i < NKSTEP; ++i) {
        if (i < NKSTEP - 1) CP_WAIT(1);
        else                CP_WAIT(0);
        __syncthreads();

        if (i + 2 < NKSTEP)
            issue_stage(sbase, i + 2, (slot + 2 >= NSTAGE) ? slot - 1 : slot + 2,
                        m0, n0, tid);

        uint32_t sS = sbase + slot * STAGE_BYTES;
        uint32_t aH = sS + AH_OFF + m_base * ROWSTRIDE + frag_off;
        uint32_t aL = sS + AL_OFF + m_base * ROWSTRIDE + frag_off;
        uint32_t bH = sS + BH_OFF + n_base * ROWSTRIDE + frag_off;
        uint32_t bL = sS + BL_OFF + n_base * ROWSTRIDE + frag_off;

        #pragma unroll
        for (int kk = 0; kk < 2; ++kk) {
            uint32_t ah[2][4], al[2][4], b[4][4];
            // ---- load A-hi + B-hi, do sub0 = Ahi x Whi ----
            #pragma unroll
            for (int mt = 0; mt < 2; ++mt)
                ldm_x4(ah[mt][0], ah[mt][1], ah[mt][2], ah[mt][3],
                       aH + mt * (16 * ROWSTRIDE) + kk * 32);
            #pragma unroll
            for (int nt = 0; nt < 4; ++nt)
                ldm_x4(b[nt][0], b[nt][1], b[nt][2], b[nt][3],
                       bH + nt * (16 * ROWSTRIDE) + kk * 32);
            #pragma unroll
            for (int mt = 0; mt < 2; ++mt)
                #pragma unroll
                for (int nt = 0; nt < 4; ++nt) {
                    mma_bf16(acc[mt][2 * nt + 0], ah[mt], b[nt][0], b[nt][2]);
                    mma_bf16(acc[mt][2 * nt + 1], ah[mt], b[nt][1], b[nt][3]);
                }
            // ---- load A-lo, do sub2 = Alo x Whi (reuse b regs) ----
            #pragma unroll
            for (int mt = 0; mt < 2; ++mt)
                ldm_x4(al[mt][0], al[mt][1], al[mt][2], al[mt][3],
                       aL + mt * (16 * ROWSTRIDE) + kk * 32);
            #pragma unroll
            for (int mt = 0; mt < 2; ++mt)
                #pragma unroll
                for (int nt = 0; nt < 4; ++nt) {
                    mma_bf16(acc[mt][2 * nt + 0], al[mt], b[nt][0], b[nt][2]);
                    mma_bf16(acc[mt][2 * nt + 1], al[mt], b[nt][1], b[nt][3]);
                }
            // ---- load B-lo into b regs, do sub1 = Ahi x Wlo ----
            #pragma unroll
            for (int nt = 0; nt < 4; ++nt)
                ldm_x4(b[nt][0], b[nt][1], b[nt][2], b[nt][3],
                       bL + nt * (16 * ROWSTRIDE) + kk * 32);
            #pragma unroll
            for (int mt = 0; mt < 2; ++mt)
                #pragma unroll
                for (int nt = 0; nt < 4; ++nt) {
                    mma_bf16(acc[mt][2 * nt + 0], ah[mt], b[nt][0], b[nt][2]);
                    mma_bf16(acc[mt][2 * nt + 1], ah[mt], b[nt][1], b[nt][3]);
                }
        }
        slot = (slot + 1 == NSTAGE) ? 0 : slot + 1;
    }

    // epilogue: c frag mapping -> y + bias
    const int g  = lane >> 2;
    const int tg = lane & 3;
    #pragma unroll
    for (int mt = 0; mt < 2; ++mt) {
        int m = m0 + m_base + mt * 16 + g;
        #pragma unroll
        for (int nt = 0; nt < 8; ++nt) {
            int n = n0 + n_base + nt * 8 + tg * 2;
            float b0 = bias[n], b1 = bias[n + 1];
            float2 v0 = make_float2(acc[mt][nt][0] + b0, acc[mt][nt][1] + b1);
            float2 v1 = make_float2(acc[mt][nt][2] + b0, acc[mt][nt][3] + b1);
            *(float2*)(y + (size_t)m * DD + n)       = v0;
            *(float2*)(y + (size_t)(m + 8) * DD + n) = v1;
        }
    }
}

// ---------------------------------------------------------------------------
// Launch
// ---------------------------------------------------------------------------
extern "C" void kernel_launch(void* const* d_in, const int* in_sizes, int n_in,
                              void* d_out, int out_size) {
    const float* x     = (const float*)d_in[0];
    const float* W_p   = (const float*)d_in[1];
    const float* W_i   = (const float*)d_in[2];
    const float* W_d   = (const float*)d_in[3];
    const float* a_log = (const float*)d_in[4];
    const float* b_log = (const float*)d_in[5];
    const float* W_gw  = (const float*)d_in[6];
    const float* W_gb  = (const float*)d_in[7];
    const float* bias  = (const float*)d_in[8];
    float* y = (float*)d_out;

    static int smem_set = 0;
    if (!smem_set) {
        cudaFuncSetAttribute(gemm_kernel,
                             cudaFuncAttributeMaxDynamicSharedMemorySize, GEMM_SMEM);
        smem_set = 1;
    }

    // 1) weight conversion (independent of scan/gate)
    {
        int n4 = DD * K3 / 4;
        wconv_kernel<<<(n4 + 255) / 256, 256>>>(W_p, W_i, W_d);
    }
    // 2) temporal scan
    scan_kernel<<<(BB * DD + 63) / 64, 64>>>(x, a_log, b_log);
    // 3) gates + split-bf16 feature emit
    gate_kernel<<<MTOT, 256>>>(x, W_gw, W_gb);
    // 4) tensor-core GEMM + bias
    dim3 grid(DD / 256, MTOT / 128);   // (8, 64)
    gemm_kernel<<<grid, 512, GEMM_SMEM>>>(bias, y);
}

// round 13
// speedup vs baseline: 4.4608x; 1.8217x over previous
#include <cuda_runtime.h>
#include <cuda_fp16.h>
#include <math.h>
#include <stdint.h>

#define DD   2048
#define K3   6144
#define BB   4
#define TT   2048
#define MTOT 8192   // B*T
#define NCHUNK 4
#define CHUNK (TT / NCHUNK)   // 512

// ---------------- scratch (device globals; no allocation) -------------------
__device__ float g_I [(size_t)MTOT * DD];     // integral  (fp32)
__device__ float g_Dv[(size_t)MTOT * DD];     // derivative(fp32)
__device__ __half g_A[(size_t)MTOT * K3];     // gated features [g0*x|g1*I|g2*D]
__device__ __half g_W[(size_t)DD * K3];       // [Wp|Wi|Wd] concatenated

// ---------------- helpers ----------------------------------------------------
__device__ __forceinline__ uint32_t smem_u32(const void* p) {
    uint32_t a;
    asm("{ .reg .u64 t; cvta.to.shared.u64 t, %1; cvt.u32.u64 %0, t; }"
        : "=r"(a) : "l"(p));
    return a;
}
__device__ __forceinline__ void cp16(uint32_t dst, const void* src) {
    asm volatile("cp.async.cg.shared.global [%0], [%1], 16;\n"
                 :: "r"(dst), "l"(src));
}
#define CP_COMMIT()  asm volatile("cp.async.commit_group;\n" ::: "memory")
#define CP_WAIT(n)   asm volatile("cp.async.wait_group %0;\n" :: "n"(n) : "memory")

__device__ __forceinline__ void ldm_x4(uint32_t& r0, uint32_t& r1,
                                       uint32_t& r2, uint32_t& r3, uint32_t addr) {
    asm volatile("ldmatrix.sync.aligned.m8n8.x4.shared.b16 {%0,%1,%2,%3}, [%4];"
                 : "=r"(r0), "=r"(r1), "=r"(r2), "=r"(r3) : "r"(addr));
}
__device__ __forceinline__ void mma_f16(float* c, const uint32_t* a,
                                        uint32_t b0, uint32_t b1) {
    asm volatile(
        "mma.sync.aligned.m16n8k16.row.col.f32.f16.f16.f32 "
        "{%0,%1,%2,%3}, {%4,%5,%6,%7}, {%8,%9}, {%0,%1,%2,%3};"
        : "+f"(c[0]), "+f"(c[1]), "+f"(c[2]), "+f"(c[3])
        : "r"(a[0]), "r"(a[1]), "r"(a[2]), "r"(a[3]), "r"(b0), "r"(b1));
}

// ---------------------------------------------------------------------------
// Kernel 1a: chunked temporal scan (local pass). T split into NCHUNK chunks;
// each thread scans one chunk of one (b,d) channel with carry-in 0 (the true
// carry is added by the fixup kernel — the recurrences are linear).
// x_prev at a chunk boundary is read directly (exact).
// ---------------------------------------------------------------------------
__global__ void scan_local_kernel(const float* __restrict__ x,
                                  const float* __restrict__ alpha_logit,
                                  const float* __restrict__ beta_logit) {
    int idx = blockIdx.x * blockDim.x + threadIdx.x;
    if (idx >= BB * DD * NCHUNK) return;
    int d  = idx & (DD - 1);
    int bc = idx >> 11;
    int b  = bc & (BB - 1);
    int c  = bc >> 2;

    float a  = 1.0f / (1.0f + expf(-alpha_logit[d]));
    float be = 1.0f / (1.0f + expf(-beta_logit[d]));
    float one_a  = 1.0f - a;
    float one_be = 1.0f - be;

    size_t base = ((size_t)b * TT + (size_t)c * CHUNK) * DD + d;
    const float* xp = x + base;
    float* Ip = g_I  + base;
    float* Dp = g_Dv + base;

    float xprev = (c == 0) ? 0.0f : x[base - DD];
    float s = 0.0f, dv = 0.0f;
    #pragma unroll 8
    for (int t = 0; t < CHUNK; ++t) {
        float xt = xp[(size_t)t * DD];
        s  = a  * s  + one_a  * xt;
        dv = be * dv + one_be * (xt - xprev);
        xprev = xt;
        Ip[(size_t)t * DD] = s;
        Dp[(size_t)t * DD] = dv;
    }
}

// ---------------------------------------------------------------------------
// Kernel 1b: scan fixup. For chunk c>0, element j gets += factor^(j+1) * carry
// from the previous chunk's (corrected) final state. Truncate when the factor
// drops below 1e-10 (abs err <= 1e-9, far below fp32 noise of O(1) values).
// One thread per (b,d); loads are coalesced across d.
// ---------------------------------------------------------------------------
__global__ void scan_fix_kernel(const float* __restrict__ alpha_logit,
                                const float* __restrict__ beta_logit) {
    int idx = blockIdx.x * blockDim.x + threadIdx.x;
    if (idx >= BB * DD) return;
    int d = idx & (DD - 1);
    int b = idx >> 11;

    float a  = 1.0f / (1.0f + expf(-alpha_logit[d]));
    float be = 1.0f / (1.0f + expf(-beta_logit[d]));

    float* Ip = g_I  + (size_t)b * TT * DD + d;
    float* Dp = g_Dv + (size_t)b * TT * DD + d;

    float S  = Ip[(size_t)(CHUNK - 1) * DD];   // chunk 0 final (exact)
    float Dv = Dp[(size_t)(CHUNK - 1) * DD];

    for (int c = 1; c < NCHUNK; ++c) {
        float* Ic = Ip + (size_t)c * CHUNK * DD;
        float* Dc = Dp + (size_t)c * CHUNK * DD;
        float fa = a;
        for (int j = 0; j < CHUNK && fa > 1e-10f; ++j) {
            Ic[(size_t)j * DD] += fa * S;
            fa *= a;
        }
        float fb = be;
        for (int j = 0; j < CHUNK && fb > 1e-10f; ++j) {
            Dc[(size_t)j * DD] += fb * Dv;
            fb *= be;
        }
        S  = Ic[(size_t)(CHUNK - 1) * DD];     // corrected final = true carry
        Dv = Dc[(size_t)(CHUNK - 1) * DD];
    }
}

// ---------------------------------------------------------------------------
// Kernel 2: W -> concatenated fp16: W'[o, 0:2048|2048:4096|4096:6144]
// ---------------------------------------------------------------------------
__global__ void wconv_kernel(const float* __restrict__ Wp,
                             const float* __restrict__ Wi,
                             const float* __restrict__ Wd) {
    size_t i4 = (size_t)blockIdx.x * blockDim.x + threadIdx.x;
    if (i4 >= (size_t)DD * K3 / 4) return;
    size_t idx = i4 * 4;
    int o = (int)(idx / K3);
    int k = (int)(idx % K3);
    const float* src = (k < DD)     ? Wp + (size_t)o * DD + k
                     : (k < 2 * DD) ? Wi + (size_t)o * DD + (k - DD)
                                    : Wd + (size_t)o * DD + (k - 2 * DD);
    float4 v = *(const float4*)src;
    __half2* hp = (__half2*)(g_W + idx);
    hp[0] = __floats2half2_rn(v.x, v.y);
    hp[1] = __floats2half2_rn(v.z, v.w);
}

// ---------------------------------------------------------------------------
// Kernel 3: gates (fp32 softmax) + emit scaled fp16 A = [g0*x | g1*I | g2*D]
// ---------------------------------------------------------------------------
__global__ void gate_kernel(const float* __restrict__ x,
                            const float* __restrict__ Wg,
                            const float* __restrict__ Wgb) {
    int m   = blockIdx.x;
    int tid = threadIdx.x;
    const float* xr = x    + (size_t)m * DD;
    const float* Ir = g_I  + (size_t)m * DD;
    const float* Dr = g_Dv + (size_t)m * DD;

    float a0 = 0.f, a1 = 0.f, a2 = 0.f;
    for (int d = tid; d < DD; d += 256) {
        float xv = xr[d], iv = Ir[d], dv = Dr[d];
        a0 += xv * Wg[d]        + iv * Wg[DD + d]        + dv * Wg[2*DD + d];
        a1 += xv * Wg[K3 + d]   + iv * Wg[K3 + DD + d]   + dv * Wg[K3 + 2*DD + d];
        a2 += xv * Wg[2*K3 + d] + iv * Wg[2*K3 + DD + d] + dv * Wg[2*K3 + 2*DD + d];
    }

    __shared__ float r0[256], r1[256], r2[256];
    r0[tid] = a0; r1[tid] = a1; r2[tid] = a2;
    __syncthreads();
    for (int s = 128; s > 0; s >>= 1) {
        if (tid < s) { r0[tid] += r0[tid+s]; r1[tid] += r1[tid+s]; r2[tid] += r2[tid+s]; }
        __syncthreads();
    }

    __shared__ float gsm[3];
    if (tid == 0) {
        float l0 = r0[0] + Wgb[0], l1 = r1[0] + Wgb[1], l2 = r2[0] + Wgb[2];
        float mx = fmaxf(l0, fmaxf(l1, l2));
        float e0 = expf(l0 - mx), e1 = expf(l1 - mx), e2 = expf(l2 - mx);
        float inv = 1.0f / (e0 + e1 + e2);
        gsm[0] = e0 * inv; gsm[1] = e1 * inv; gsm[2] = e2 * inv;
    }
    __syncthreads();
    float g0 = gsm[0], g1 = gsm[1], g2 = gsm[2];

    __half* Ah = g_A + (size_t)m * K3;
    for (int d = tid; d < DD; d += 256) {
        Ah[d]          = __float2half_rn(g0 * xr[d]);
        Ah[DD + d]     = __float2half_rn(g1 * Ir[d]);
        Ah[2 * DD + d] = __float2half_rn(g2 * Dr[d]);
    }
}

// ---------------------------------------------------------------------------
// Kernel 4: mma.sync fp16 GEMM:  y = A * W^T + bias
// Block 128(m) x 256(n), BK=32. 512 threads = 16 warps (4m x 4n), warp 32x64.
// 5-stage cp.async pipeline (30.7KB/stage), prefetch depth 4, empty-commit
// tail so CP_WAIT(3) is always valid. 1 barrier per K-step (192 total).
// ---------------------------------------------------------------------------
#define NKSTEP 192              // K3 / 32
#define ROWSTRIDE 80
#define A_OFF 0
#define B_OFF 10240             // 128*80
#define STAGE_BYTES 30720       // A 10240 + B 20480
#define NSTAGE 5
#define GEMM_SMEM (NSTAGE * STAGE_BYTES)   // 153600

__device__ __forceinline__ void issue_stage(uint32_t sbase, int kstep, int slot,
                                            int m0, int n0, int tid) {
    const int k0 = kstep * 32;
    uint32_t sS = sbase + slot * STAGE_BYTES;

    // A tile: 128 rows x 4 chunks of 16B -> 512 ops, 1 per thread
    {
        int row = tid >> 2, c = tid & 3;
        size_t go = (((size_t)(m0 + row) * K3 + k0) << 1) + c * 16;
        cp16(sS + A_OFF + row * ROWSTRIDE + c * 16, (const char*)g_A + go);
    }
    // B tile: 256 rows x 4 chunks -> 1024 ops, 2 per thread
    #pragma unroll
    for (int q = 0; q < 2; ++q) {
        int idx = tid + q * 512;
        int row = idx >> 2, c = idx & 3;
        size_t go = (((size_t)(n0 + row) * K3 + k0) << 1) + c * 16;
        cp16(sS + B_OFF + row * ROWSTRIDE + c * 16, (const char*)g_W + go);
    }
    CP_COMMIT();
}

__global__ __launch_bounds__(512, 1)
void gemm_kernel(const float* __restrict__ bias, float* __restrict__ y) {
    extern __shared__ char smem[];
    uint32_t sbase = smem_u32(smem);
    const int tid  = threadIdx.x;
    const int wid  = tid >> 5;
    const int lane = tid & 31;
    const int n0 = blockIdx.x * 256;
    const int m0 = blockIdx.y * 128;

    const int m_base = (wid & 3) * 32;    // 4 warps along m
    const int n_base = (wid >> 2) * 64;   // 4 warps along n

    // ldmatrix per-thread pattern: row = base + (lane&15), chunk = lane>>4
    const uint32_t frag_off = (lane & 15) * ROWSTRIDE + (lane >> 4) * 16;

    float acc[2][8][4];
    #pragma unroll
    for (int i = 0; i < 2; ++i)
        #pragma unroll
        for (int j = 0; j < 8; ++j)
            #pragma unroll
            for (int q = 0; q < 4; ++q) acc[i][j][q] = 0.0f;

    // prologue: fill stages 0..3 (slot = kstep % NSTAGE throughout)
    issue_stage(sbase, 0, 0, m0, n0, tid);
    issue_stage(sbase, 1, 1, m0, n0, tid);
    issue_stage(sbase, 2, 2, m0, n0, tid);
    issue_stage(sbase, 3, 3, m0, n0, tid);

    for (int i = 0; i < NKSTEP; ++i) {
        CP_WAIT(3);                 // with one commit per iter, oldest = group i
        __syncthreads();

        int nx = i + 4;
        if (nx < NKSTEP) {
            int slot_nx = nx;       // nx % 5 without div: nx-i pattern
            slot_nx = nx - (nx / NSTAGE) * NSTAGE;
            issue_stage(sbase, nx, slot_nx, m0, n0, tid);
        } else {
            CP_COMMIT();            // empty group keeps the wait invariant
        }

        int slot = i - (i / NSTAGE) * NSTAGE;
        uint32_t sS = sbase + slot * STAGE_BYTES;
        uint32_t aA = sS + A_OFF + m_base * ROWSTRIDE + frag_off;
        uint32_t aB = sS + B_OFF + n_base * ROWSTRIDE + frag_off;

        #pragma unroll
        for (int kk = 0; kk < 2; ++kk) {
            uint32_t a[2][4], b[4][4];
            #pragma unroll
            for (int mt = 0; mt < 2; ++mt)
                ldm_x4(a[mt][0], a[mt][1], a[mt][2], a[mt][3],
                       aA + mt * (16 * ROWSTRIDE) + kk * 32);
            #pragma unroll
            for (int nt = 0; nt < 4; ++nt)
                ldm_x4(b[nt][0], b[nt][1], b[nt][2], b[nt][3],
                       aB + nt * (16 * ROWSTRIDE) + kk * 32);
            // non-trans ldmatrix on n-major B: {r0,r2} = n0-7 operand,
            // {r1,r3} = n8-15 operand (matches m16n8k16 .col B layout)
            #pragma unroll
            for (int mt = 0; mt < 2; ++mt)
                #pragma unroll
                for (int nt = 0; nt < 4; ++nt) {
                    mma_f16(acc[mt][2 * nt + 0], a[mt], b[nt][0], b[nt][2]);
                    mma_f16(acc[mt][2 * nt + 1], a[mt], b[nt][1], b[nt][3]);
                }
        }
    }

    // epilogue: c frag mapping -> y + bias
    const int g  = lane >> 2;
    const int tg = lane & 3;
    #pragma unroll
    for (int mt = 0; mt < 2; ++mt) {
        int m = m0 + m_base + mt * 16 + g;
        #pragma unroll
        for (int nt = 0; nt < 8; ++nt) {
            int n = n0 + n_base + nt * 8 + tg * 2;
            float b0 = bias[n], b1 = bias[n + 1];
            float2 v0 = make_float2(acc[mt][nt][0] + b0, acc[mt][nt][1] + b1);
            float2 v1 = make_float2(acc[mt][nt][2] + b0, acc[mt][nt][3] + b1);
            *(float2*)(y + (size_t)m * DD + n)       = v0;
            *(float2*)(y + (size_t)(m + 8) * DD + n) = v1;
        }
    }
}

// ---------------------------------------------------------------------------
// Launch
// ---------------------------------------------------------------------------
extern "C" void kernel_launch(void* const* d_in, const int* in_sizes, int n_in,
                              void* d_out, int out_size) {
    const float* x     = (const float*)d_in[0];
    const float* W_p   = (const float*)d_in[1];
    const float* W_i   = (const float*)d_in[2];
    const float* W_d   = (const float*)d_in[3];
    const float* a_log = (const float*)d_in[4];
    const float* b_log = (const float*)d_in[5];
    const float* W_gw  = (const float*)d_in[6];
    const float* W_gb  = (const float*)d_in[7];
    const float* bias  = (const float*)d_in[8];
    float* y = (float*)d_out;

    cudaFuncSetAttribute(gemm_kernel,
                         cudaFuncAttributeMaxDynamicSharedMemorySize, GEMM_SMEM);

    // 1) weight conversion (independent of scan/gate)
    {
        int n4 = DD * K3 / 4;
        wconv_kernel<<<(n4 + 255) / 256, 256>>>(W_p, W_i, W_d);
    }
    // 2) chunked temporal scan + carry fixup
    scan_local_kernel<<<(BB * DD * NCHUNK + 127) / 128, 128>>>(x, a_log, b_log);
    scan_fix_kernel<<<(BB * DD + 127) / 128, 128>>>(a_log, b_log);
    // 3) gates + fp16 feature emit
    gate_kernel<<<MTOT, 256>>>(x, W_gw, W_gb);
    // 4) tensor-core GEMM + bias
    dim3 grid(DD / 256, MTOT / 128);   // (8, 64)
    gemm_kernel<<<grid, 512, GEMM_SMEM>>>(bias, y);
}

// round 15
// speedup vs baseline: 5.1770x; 1.1605x over previous
#include <cuda_runtime.h>
#include <cuda_fp16.h>
#include <math.h>
#include <stdint.h>

#define DD   2048
#define K3   6144
#define BB   4
#define TT   2048
#define MTOT 8192   // B*T
#define NCHUNK 4
#define CHUNK (TT / NCHUNK)   // 512

// ---------------- scratch (device globals; no allocation) -------------------
__device__ float g_I [(size_t)MTOT * DD];     // integral  (fp32)
__device__ float g_Dv[(size_t)MTOT * DD];     // derivative(fp32)
__device__ __half g_A[(size_t)MTOT * K3];     // gated features [g0*x|g1*I|g2*D]
__device__ __half g_W[(size_t)DD * K3];       // [Wp|Wi|Wd] concatenated

// ---------------- helpers ----------------------------------------------------
__device__ __forceinline__ uint32_t smem_u32(const void* p) {
    uint32_t a;
    asm("{ .reg .u64 t; cvta.to.shared.u64 t, %1; cvt.u32.u64 %0, t; }"
        : "=r"(a) : "l"(p));
    return a;
}
__device__ __forceinline__ void cp16(uint32_t dst, const void* src) {
    asm volatile("cp.async.cg.shared.global [%0], [%1], 16;\n"
                 :: "r"(dst), "l"(src));
}
#define CP_COMMIT()  asm volatile("cp.async.commit_group;\n" ::: "memory")
#define CP_WAIT(n)   asm volatile("cp.async.wait_group %0;\n" :: "n"(n) : "memory")

__device__ __forceinline__ void ldm_x4(uint32_t& r0, uint32_t& r1,
                                       uint32_t& r2, uint32_t& r3, uint32_t addr) {
    asm volatile("ldmatrix.sync.aligned.m8n8.x4.shared.b16 {%0,%1,%2,%3}, [%4];"
                 : "=r"(r0), "=r"(r1), "=r"(r2), "=r"(r3) : "r"(addr));
}
__device__ __forceinline__ void mma_f16(float* c, const uint32_t* a,
                                        uint32_t b0, uint32_t b1) {
    asm volatile(
        "mma.sync.aligned.m16n8k16.row.col.f32.f16.f16.f32 "
        "{%0,%1,%2,%3}, {%4,%5,%6,%7}, {%8,%9}, {%0,%1,%2,%3};"
        : "+f"(c[0]), "+f"(c[1]), "+f"(c[2]), "+f"(c[3])
        : "r"(a[0]), "r"(a[1]), "r"(a[2]), "r"(a[3]), "r"(b0), "r"(b1));
}

// ---------------------------------------------------------------------------
// Kernel 1a: chunked temporal scan (local pass). T split into NCHUNK chunks;
// each thread scans one chunk of one (b,d) channel with carry-in 0 (the true
// carry is added by the fixup kernel — the recurrences are linear).
// ---------------------------------------------------------------------------
__global__ void scan_local_kernel(const float* __restrict__ x,
                                  const float* __restrict__ alpha_logit,
                                  const float* __restrict__ beta_logit) {
    int idx = blockIdx.x * blockDim.x + threadIdx.x;
    if (idx >= BB * DD * NCHUNK) return;
    int d  = idx & (DD - 1);
    int bc = idx >> 11;
    int b  = bc & (BB - 1);
    int c  = bc >> 2;

    float a  = 1.0f / (1.0f + expf(-alpha_logit[d]));
    float be = 1.0f / (1.0f + expf(-beta_logit[d]));
    float one_a  = 1.0f - a;
    float one_be = 1.0f - be;

    size_t base = ((size_t)b * TT + (size_t)c * CHUNK) * DD + d;
    const float* xp = x + base;
    float* Ip = g_I  + base;
    float* Dp = g_Dv + base;

    float xprev = (c == 0) ? 0.0f : x[base - DD];
    float s = 0.0f, dv = 0.0f;
    #pragma unroll 8
    for (int t = 0; t < CHUNK; ++t) {
        float xt = xp[(size_t)t * DD];
        s  = a  * s  + one_a  * xt;
        dv = be * dv + one_be * (xt - xprev);
        xprev = xt;
        Ip[(size_t)t * DD] = s;
        Dp[(size_t)t * DD] = dv;
    }
}

// ---------------------------------------------------------------------------
// Kernel 1b: scan fixup. Chunk c>0 element j gets += factor^(j+1) * carry.
// Truncated when factor < 1e-10 (abs err <= 1e-9).
// ---------------------------------------------------------------------------
__global__ void scan_fix_kernel(const float* __restrict__ alpha_logit,
                                const float* __restrict__ beta_logit) {
    int idx = blockIdx.x * blockDim.x + threadIdx.x;
    if (idx >= BB * DD) return;
    int d = idx & (DD - 1);
    int b = idx >> 11;

    float a  = 1.0f / (1.0f + expf(-alpha_logit[d]));
    float be = 1.0f / (1.0f + expf(-beta_logit[d]));

    float* Ip = g_I  + (size_t)b * TT * DD + d;
    float* Dp = g_Dv + (size_t)b * TT * DD + d;

    float S  = Ip[(size_t)(CHUNK - 1) * DD];
    float Dv = Dp[(size_t)(CHUNK - 1) * DD];

    for (int c = 1; c < NCHUNK; ++c) {
        float* Ic = Ip + (size_t)c * CHUNK * DD;
        float* Dc = Dp + (size_t)c * CHUNK * DD;
        float fa = a;
        for (int j = 0; j < CHUNK && fa > 1e-10f; ++j) {
            Ic[(size_t)j * DD] += fa * S;
            fa *= a;
        }
        float fb = be;
        for (int j = 0; j < CHUNK && fb > 1e-10f; ++j) {
            Dc[(size_t)j * DD] += fb * Dv;
            fb *= be;
        }
        S  = Ic[(size_t)(CHUNK - 1) * DD];
        Dv = Dc[(size_t)(CHUNK - 1) * DD];
    }
}

// ---------------------------------------------------------------------------
// Kernel 2: W -> concatenated fp16: W'[o, 0:2048|2048:4096|4096:6144]
// ---------------------------------------------------------------------------
__global__ void wconv_kernel(const float* __restrict__ Wp,
                             const float* __restrict__ Wi,
                             const float* __restrict__ Wd) {
    size_t i4 = (size_t)blockIdx.x * blockDim.x + threadIdx.x;
    if (i4 >= (size_t)DD * K3 / 4) return;
    size_t idx = i4 * 4;
    int o = (int)(idx / K3);
    int k = (int)(idx % K3);
    const float* src = (k < DD)     ? Wp + (size_t)o * DD + k
                     : (k < 2 * DD) ? Wi + (size_t)o * DD + (k - DD)
                                    : Wd + (size_t)o * DD + (k - 2 * DD);
    float4 v = *(const float4*)src;
    __half2* hp = (__half2*)(g_W + idx);
    hp[0] = __floats2half2_rn(v.x, v.y);
    hp[1] = __floats2half2_rn(v.z, v.w);
}

// ---------------------------------------------------------------------------
// Kernel 3: gates + fp16 emit, register-fused. 256 threads/row; each thread
// holds exactly 2 float4 of x/I/D (DD/4 = 512 = 256*2) across the softmax
// reduction, then emits fp16 from registers — no second global read.
// ---------------------------------------------------------------------------
__global__ __launch_bounds__(256)
void gate_kernel(const float* __restrict__ x,
                 const float* __restrict__ Wg,
                 const float* __restrict__ Wgb) {
    int m    = blockIdx.x;
    int tid  = threadIdx.x;
    int lane = tid & 31;
    int wrp  = tid >> 5;

    const float4* xr = (const float4*)(x    + (size_t)m * DD);
    const float4* Ir = (const float4*)(g_I  + (size_t)m * DD);
    const float4* Dr = (const float4*)(g_Dv + (size_t)m * DD);
    const float4* W0 = (const float4*)Wg;               // gate row 0
    const float4* W1 = (const float4*)(Wg + K3);        // gate row 1
    const float4* W2 = (const float4*)(Wg + 2 * K3);    // gate row 2

    float4 xv[2], iv[2], dv[2];
    float a0 = 0.f, a1 = 0.f, a2 = 0.f;
    #pragma unroll
    for (int it = 0; it < 2; ++it) {
        int q = tid + it * 256;            // float4 index within the row
        xv[it] = xr[q]; iv[it] = Ir[q]; dv[it] = Dr[q];
        float4 wa, wb, wc;
        wa = W0[q]; wb = W0[q + 512]; wc = W0[q + 1024];
        a0 += xv[it].x*wa.x + xv[it].y*wa.y + xv[it].z*wa.z + xv[it].w*wa.w
            + iv[it].x*wb.x + iv[it].y*wb.y + iv[it].z*wb.z + iv[it].w*wb.w
            + dv[it].x*wc.x + dv[it].y*wc.y + dv[it].z*wc.z + dv[it].w*wc.w;
        wa = W1[q]; wb = W1[q + 512]; wc = W1[q + 1024];
        a1 += xv[it].x*wa.x + xv[it].y*wa.y + xv[it].z*wa.z + xv[it].w*wa.w
            + iv[it].x*wb.x + iv[it].y*wb.y + iv[it].z*wb.z + iv[it].w*wb.w
            + dv[it].x*wc.x + dv[it].y*wc.y + dv[it].z*wc.z + dv[it].w*wc.w;
        wa = W2[q]; wb = W2[q + 512]; wc = W2[q + 1024];
        a2 += xv[it].x*wa.x + xv[it].y*wa.y + xv[it].z*wa.z + xv[it].w*wa.w
            + iv[it].x*wb.x + iv[it].y*wb.y + iv[it].z*wb.z + iv[it].w*wb.w
            + dv[it].x*wc.x + dv[it].y*wc.y + dv[it].z*wc.z + dv[it].w*wc.w;
    }

    // warp reduce then cross-warp combine
    #pragma unroll
    for (int off = 16; off; off >>= 1) {
        a0 += __shfl_xor_sync(0xFFFFFFFFu, a0, off);
        a1 += __shfl_xor_sync(0xFFFFFFFFu, a1, off);
        a2 += __shfl_xor_sync(0xFFFFFFFFu, a2, off);
    }
    __shared__ float red[8][3];
    __shared__ float gsm[3];
    if (lane == 0) { red[wrp][0] = a0; red[wrp][1] = a1; red[wrp][2] = a2; }
    __syncthreads();
    if (tid == 0) {
        float l0 = Wgb[0], l1 = Wgb[1], l2 = Wgb[2];
        #pragma unroll
        for (int w = 0; w < 8; ++w) { l0 += red[w][0]; l1 += red[w][1]; l2 += red[w][2]; }
        float mx = fmaxf(l0, fmaxf(l1, l2));
        float e0 = expf(l0 - mx), e1 = expf(l1 - mx), e2 = expf(l2 - mx);
        float inv = 1.0f / (e0 + e1 + e2);
        gsm[0] = e0 * inv; gsm[1] = e1 * inv; gsm[2] = e2 * inv;
    }
    __syncthreads();
    float g0 = gsm[0], g1 = gsm[1], g2 = gsm[2];

    // emit from registers: 4 halves (uint2) per float4
    __half* Ah = g_A + (size_t)m * K3;
    #pragma unroll
    for (int it = 0; it < 2; ++it) {
        int e = (tid + it * 256) * 4;      // element offset in row segment
        uint2 o;
        __half2 h0 = __floats2half2_rn(g0 * xv[it].x, g0 * xv[it].y);
        __half2 h1 = __floats2half2_rn(g0 * xv[it].z, g0 * xv[it].w);
        o.x = *(uint32_t*)&h0; o.y = *(uint32_t*)&h1;
        *(uint2*)(Ah + e) = o;
        h0 = __floats2half2_rn(g1 * iv[it].x, g1 * iv[it].y);
        h1 = __floats2half2_rn(g1 * iv[it].z, g1 * iv[it].w);
        o.x = *(uint32_t*)&h0; o.y = *(uint32_t*)&h1;
        *(uint2*)(Ah + DD + e) = o;
        h0 = __floats2half2_rn(g2 * dv[it].x, g2 * dv[it].y);
        h1 = __floats2half2_rn(g2 * dv[it].z, g2 * dv[it].w);
        o.x = *(uint32_t*)&h0; o.y = *(uint32_t*)&h1;
        *(uint2*)(Ah + 2 * DD + e) = o;
    }
}

// ---------------------------------------------------------------------------
// Kernel 4: mma.sync fp16 GEMM:  y = A * W^T + bias
// Block 128(m) x 128(n), BK=32. 256 threads = 8 warps (4m x 2n), warp 32x64.
// 5-stage cp.async pipeline (20.5KB/stage = 102.4KB), TWO CTAs per SM so
// barrier/wait stalls of one CTA are hidden by the other.
// ---------------------------------------------------------------------------
#define NKSTEP 192              // K3 / 32
#define ROWSTRIDE 80
#define A_OFF 0
#define B_OFF 10240             // 128*80
#define STAGE_BYTES 20480       // A 10240 + B 10240
#define NSTAGE 5
#define GEMM_SMEM (NSTAGE * STAGE_BYTES)   // 102400

__device__ __forceinline__ void issue_stage(uint32_t sbase, int kstep, int slot,
                                            int m0, int n0, int tid) {
    const int k0 = kstep * 32;
    uint32_t sS = sbase + slot * STAGE_BYTES;

    // A tile: 128 rows x 4 chunks of 16B -> 512 ops, 2 per thread
    #pragma unroll
    for (int q = 0; q < 2; ++q) {
        int idx = tid + q * 256;
        int row = idx >> 2, c = idx & 3;
        size_t go = (((size_t)(m0 + row) * K3 + k0) << 1) + c * 16;
        cp16(sS + A_OFF + row * ROWSTRIDE + c * 16, (const char*)g_A + go);
    }
    // B tile: 128 rows x 4 chunks -> 512 ops, 2 per thread
    #pragma unroll
    for (int q = 0; q < 2; ++q) {
        int idx = tid + q * 256;
        int row = idx >> 2, c = idx & 3;
        size_t go = (((size_t)(n0 + row) * K3 + k0) << 1) + c * 16;
        cp16(sS + B_OFF + row * ROWSTRIDE + c * 16, (const char*)g_W + go);
    }
    CP_COMMIT();
}

__global__ __launch_bounds__(256, 2)
void gemm_kernel(const float* __restrict__ bias, float* __restrict__ y) {
    extern __shared__ char smem[];
    uint32_t sbase = smem_u32(smem);
    const int tid  = threadIdx.x;
    const int wid  = tid >> 5;
    const int lane = tid & 31;
    const int n0 = blockIdx.x * 128;
    const int m0 = blockIdx.y * 128;

    const int m_base = (wid & 3) * 32;    // 4 warps along m
    const int n_base = (wid >> 2) * 64;   // 2 warps along n

    // ldmatrix per-thread pattern: row = base + (lane&15), chunk = lane>>4
    const uint32_t frag_off = (lane & 15) * ROWSTRIDE + (lane >> 4) * 16;

    float acc[2][8][4];
    #pragma unroll
    for (int i = 0; i < 2; ++i)
        #pragma unroll
        for (int j = 0; j < 8; ++j)
            #pragma unroll
            for (int q = 0; q < 4; ++q) acc[i][j][q] = 0.0f;

    // prologue: fill stages 0..3 (slot = kstep % NSTAGE throughout)
    issue_stage(sbase, 0, 0, m0, n0, tid);
    issue_stage(sbase, 1, 1, m0, n0, tid);
    issue_stage(sbase, 2, 2, m0, n0, tid);
    issue_stage(sbase, 3, 3, m0, n0, tid);

    for (int i = 0; i < NKSTEP; ++i) {
        CP_WAIT(3);                 // one commit per iter -> oldest = group i
        __syncthreads();

        int nx = i + 4;
        if (nx < NKSTEP) {
            int slot_nx = nx - (nx / NSTAGE) * NSTAGE;
            issue_stage(sbase, nx, slot_nx, m0, n0, tid);
        } else {
            CP_COMMIT();            // empty group keeps the wait invariant
        }

        int slot = i - (i / NSTAGE) * NSTAGE;
        uint32_t sS = sbase + slot * STAGE_BYTES;
        uint32_t aA = sS + A_OFF + m_base * ROWSTRIDE + frag_off;
        uint32_t aB = sS + B_OFF + n_base * ROWSTRIDE + frag_off;

        #pragma unroll
        for (int kk = 0; kk < 2; ++kk) {
            uint32_t a[2][4], b[4][4];
            #pragma unroll
            for (int mt = 0; mt < 2; ++mt)
                ldm_x4(a[mt][0], a[mt][1], a[mt][2], a[mt][3],
                       aA + mt * (16 * ROWSTRIDE) + kk * 32);
            #pragma unroll
            for (int nt = 0; nt < 4; ++nt)
                ldm_x4(b[nt][0], b[nt][1], b[nt][2], b[nt][3],
                       aB + nt * (16 * ROWSTRIDE) + kk * 32);
            // non-trans ldmatrix on n-major B: {r0,r2} = n0-7 operand,
            // {r1,r3} = n8-15 operand (matches m16n8k16 .col B layout)
            #pragma unroll
            for (int mt = 0; mt < 2; ++mt)
                #pragma unroll
                for (int nt = 0; nt < 4; ++nt) {
                    mma_f16(acc[mt][2 * nt + 0], a[mt], b[nt][0], b[nt][2]);
                    mma_f16(acc[mt][2 * nt + 1], a[mt], b[nt][1], b[nt][3]);
                }
        }
    }

    // epilogue: c frag mapping -> y + bias
    const int g  = lane >> 2;
    const int tg = lane & 3;
    #pragma unroll
    for (int mt = 0; mt < 2; ++mt) {
        int m = m0 + m_base + mt * 16 + g;
        #pragma unroll
        for (int nt = 0; nt < 8; ++nt) {
            int n = n0 + n_base + nt * 8 + tg * 2;
            float b0 = bias[n], b1 = bias[n + 1];
            float2 v0 = make_float2(acc[mt][nt][0] + b0, acc[mt][nt][1] + b1);
            float2 v1 = make_float2(acc[mt][nt][2] + b0, acc[mt][nt][3] + b1);
            *(float2*)(y + (size_t)m * DD + n)       = v0;
            *(float2*)(y + (size_t)(m + 8) * DD + n) = v1;
        }
    }
}

// ---------------------------------------------------------------------------
// Launch
// ---------------------------------------------------------------------------
extern "C" void kernel_launch(void* const* d_in, const int* in_sizes, int n_in,
                              void* d_out, int out_size) {
    const float* x     = (const float*)d_in[0];
    const float* W_p   = (const float*)d_in[1];
    const float* W_i   = (const float*)d_in[2];
    const float* W_d   = (const float*)d_in[3];
    const float* a_log = (const float*)d_in[4];
    const float* b_log = (const float*)d_in[5];
    const float* W_gw  = (const float*)d_in[6];
    const float* W_gb  = (const float*)d_in[7];
    const float* bias  = (const float*)d_in[8];
    float* y = (float*)d_out;

    cudaFuncSetAttribute(gemm_kernel,
                         cudaFuncAttributeMaxDynamicSharedMemorySize, GEMM_SMEM);

    // 1) weight conversion (independent of scan/gate)
    {
        int n4 = DD * K3 / 4;
        wconv_kernel<<<(n4 + 255) / 256, 256>>>(W_p, W_i, W_d);
    }
    // 2) chunked temporal scan + carry fixup
    scan_local_kernel<<<(BB * DD * NCHUNK + 127) / 128, 128>>>(x, a_log, b_log);
    scan_fix_kernel<<<(BB * DD + 127) / 128, 128>>>(a_log, b_log);
    // 3) gates + fp16 feature emit (register-fused)
    gate_kernel<<<MTOT, 256>>>(x, W_gw, W_gb);
    // 4) tensor-core GEMM + bias, 2 CTAs/SM
    dim3 grid(DD / 128, MTOT / 128);   // (16, 64) = 1024 blocks
    gemm_kernel<<<grid, 256, GEMM_SMEM>>>(bias, y);
}

// round 16
// speedup vs baseline: 5.4902x; 1.0605x over previous
#include <cuda_runtime.h>
#include <cuda_fp16.h>
#include <math.h>
#include <stdint.h>

#define DD   2048
#define K3   6144
#define BB   4
#define TT   2048
#define MTOT 8192   // B*T
#define NCHUNK 4
#define CHUNK (TT / NCHUNK)   // 512

// ---------------- scratch (device globals; no allocation) -------------------
__device__ float g_I [(size_t)MTOT * DD];     // integral  (fp32)
__device__ float g_Dv[(size_t)MTOT * DD];     // derivative(fp32)
__device__ __half g_A[(size_t)MTOT * K3];     // gated features [g0*x|g1*I|g2*D]
__device__ __half g_W[(size_t)DD * K3];       // [Wp|Wi|Wd] concatenated

// ---------------- helpers ----------------------------------------------------
__device__ __forceinline__ uint32_t smem_u32(const void* p) {
    uint32_t a;
    asm("{ .reg .u64 t; cvta.to.shared.u64 t, %1; cvt.u32.u64 %0, t; }"
        : "=r"(a) : "l"(p));
    return a;
}
__device__ __forceinline__ void cp16(uint32_t dst, const void* src) {
    asm volatile("cp.async.cg.shared.global [%0], [%1], 16;\n"
                 :: "r"(dst), "l"(src));
}
#define CP_COMMIT()  asm volatile("cp.async.commit_group;\n" ::: "memory")
#define CP_WAIT(n)   asm volatile("cp.async.wait_group %0;\n" :: "n"(n) : "memory")

__device__ __forceinline__ void ldm_x4(uint32_t* r, uint32_t addr) {
    asm volatile("ldmatrix.sync.aligned.m8n8.x4.shared.b16 {%0,%1,%2,%3}, [%4];"
                 : "=r"(r[0]), "=r"(r[1]), "=r"(r[2]), "=r"(r[3]) : "r"(addr));
}
__device__ __forceinline__ void mma_f16(float* c, const uint32_t* a,
                                        uint32_t b0, uint32_t b1) {
    asm volatile(
        "mma.sync.aligned.m16n8k16.row.col.f32.f16.f16.f32 "
        "{%0,%1,%2,%3}, {%4,%5,%6,%7}, {%8,%9}, {%0,%1,%2,%3};"
        : "+f"(c[0]), "+f"(c[1]), "+f"(c[2]), "+f"(c[3])
        : "r"(a[0]), "r"(a[1]), "r"(a[2]), "r"(a[3]), "r"(b0), "r"(b1));
}

// ---------------------------------------------------------------------------
// Kernel 1a: chunked temporal scan (local pass).
// ---------------------------------------------------------------------------
__global__ void scan_local_kernel(const float* __restrict__ x,
                                  const float* __restrict__ alpha_logit,
                                  const float* __restrict__ beta_logit) {
    int idx = blockIdx.x * blockDim.x + threadIdx.x;
    if (idx >= BB * DD * NCHUNK) return;
    int d  = idx & (DD - 1);
    int bc = idx >> 11;
    int b  = bc & (BB - 1);
    int c  = bc >> 2;

    float a  = 1.0f / (1.0f + expf(-alpha_logit[d]));
    float be = 1.0f / (1.0f + expf(-beta_logit[d]));
    float one_a  = 1.0f - a;
    float one_be = 1.0f - be;

    size_t base = ((size_t)b * TT + (size_t)c * CHUNK) * DD + d;
    const float* xp = x + base;
    float* Ip = g_I  + base;
    float* Dp = g_Dv + base;

    float xprev = (c == 0) ? 0.0f : x[base - DD];
    float s = 0.0f, dv = 0.0f;
    #pragma unroll 8
    for (int t = 0; t < CHUNK; ++t) {
        float xt = xp[(size_t)t * DD];
        s  = a  * s  + one_a  * xt;
        dv = be * dv + one_be * (xt - xprev);
        xprev = xt;
        Ip[(size_t)t * DD] = s;
        Dp[(size_t)t * DD] = dv;
    }
}

// ---------------------------------------------------------------------------
// Kernel 1b: scan fixup (linear recurrences; truncated geometric correction).
// ---------------------------------------------------------------------------
__global__ void scan_fix_kernel(const float* __restrict__ alpha_logit,
                                const float* __restrict__ beta_logit) {
    int idx = blockIdx.x * blockDim.x + threadIdx.x;
    if (idx >= BB * DD) return;
    int d = idx & (DD - 1);
    int b = idx >> 11;

    float a  = 1.0f / (1.0f + expf(-alpha_logit[d]));
    float be = 1.0f / (1.0f + expf(-beta_logit[d]));

    float* Ip = g_I  + (size_t)b * TT * DD + d;
    float* Dp = g_Dv + (size_t)b * TT * DD + d;

    float S  = Ip[(size_t)(CHUNK - 1) * DD];
    float Dv = Dp[(size_t)(CHUNK - 1) * DD];

    for (int c = 1; c < NCHUNK; ++c) {
        float* Ic = Ip + (size_t)c * CHUNK * DD;
        float* Dc = Dp + (size_t)c * CHUNK * DD;
        float fa = a;
        for (int j = 0; j < CHUNK && fa > 1e-10f; ++j) {
            Ic[(size_t)j * DD] += fa * S;
            fa *= a;
        }
        float fb = be;
        for (int j = 0; j < CHUNK && fb > 1e-10f; ++j) {
            Dc[(size_t)j * DD] += fb * Dv;
            fb *= be;
        }
        S  = Ic[(size_t)(CHUNK - 1) * DD];
        Dv = Dc[(size_t)(CHUNK - 1) * DD];
    }
}

// ---------------------------------------------------------------------------
// Kernel 2: W -> concatenated fp16: W'[o, 0:2048|2048:4096|4096:6144]
// ---------------------------------------------------------------------------
__global__ void wconv_kernel(const float* __restrict__ Wp,
                             const float* __restrict__ Wi,
                             const float* __restrict__ Wd) {
    size_t i4 = (size_t)blockIdx.x * blockDim.x + threadIdx.x;
    if (i4 >= (size_t)DD * K3 / 4) return;
    size_t idx = i4 * 4;
    int o = (int)(idx / K3);
    int k = (int)(idx % K3);
    const float* src = (k < DD)     ? Wp + (size_t)o * DD + k
                     : (k < 2 * DD) ? Wi + (size_t)o * DD + (k - DD)
                                    : Wd + (size_t)o * DD + (k - 2 * DD);
    float4 v = *(const float4*)src;
    __half2* hp = (__half2*)(g_W + idx);
    hp[0] = __floats2half2_rn(v.x, v.y);
    hp[1] = __floats2half2_rn(v.z, v.w);
}

// ---------------------------------------------------------------------------
// Kernel 3: gates + fp16 emit, register-fused (one global read of x/I/D).
// ---------------------------------------------------------------------------
__global__ __launch_bounds__(256)
void gate_kernel(const float* __restrict__ x,
                 const float* __restrict__ Wg,
                 const float* __restrict__ Wgb) {
    int m    = blockIdx.x;
    int tid  = threadIdx.x;
    int lane = tid & 31;
    int wrp  = tid >> 5;

    const float4* xr = (const float4*)(x    + (size_t)m * DD);
    const float4* Ir = (const float4*)(g_I  + (size_t)m * DD);
    const float4* Dr = (const float4*)(g_Dv + (size_t)m * DD);
    const float4* W0 = (const float4*)Wg;
    const float4* W1 = (const float4*)(Wg + K3);
    const float4* W2 = (const float4*)(Wg + 2 * K3);

    float4 xv[2], iv[2], dv[2];
    float a0 = 0.f, a1 = 0.f, a2 = 0.f;
    #pragma unroll
    for (int it = 0; it < 2; ++it) {
        int q = tid + it * 256;
        xv[it] = xr[q]; iv[it] = Ir[q]; dv[it] = Dr[q];
        float4 wa, wb, wc;
        wa = W0[q]; wb = W0[q + 512]; wc = W0[q + 1024];
        a0 += xv[it].x*wa.x + xv[it].y*wa.y + xv[it].z*wa.z + xv[it].w*wa.w
            + iv[it].x*wb.x + iv[it].y*wb.y + iv[it].z*wb.z + iv[it].w*wb.w
            + dv[it].x*wc.x + dv[it].y*wc.y + dv[it].z*wc.z + dv[it].w*wc.w;
        wa = W1[q]; wb = W1[q + 512]; wc = W1[q + 1024];
        a1 += xv[it].x*wa.x + xv[it].y*wa.y + xv[it].z*wa.z + xv[it].w*wa.w
            + iv[it].x*wb.x + iv[it].y*wb.y + iv[it].z*wb.z + iv[it].w*wb.w
            + dv[it].x*wc.x + dv[it].y*wc.y + dv[it].z*wc.z + dv[it].w*wc.w;
        wa = W2[q]; wb = W2[q + 512]; wc = W2[q + 1024];
        a2 += xv[it].x*wa.x + xv[it].y*wa.y + xv[it].z*wa.z + xv[it].w*wa.w
            + iv[it].x*wb.x + iv[it].y*wb.y + iv[it].z*wb.z + iv[it].w*wb.w
            + dv[it].x*wc.x + dv[it].y*wc.y + dv[it].z*wc.z + dv[it].w*wc.w;
    }

    #pragma unroll
    for (int off = 16; off; off >>= 1) {
        a0 += __shfl_xor_sync(0xFFFFFFFFu, a0, off);
        a1 += __shfl_xor_sync(0xFFFFFFFFu, a1, off);
        a2 += __shfl_xor_sync(0xFFFFFFFFu, a2, off);
    }
    __shared__ float red[8][3];
    __shared__ float gsm[3];
    if (lane == 0) { red[wrp][0] = a0; red[wrp][1] = a1; red[wrp][2] = a2; }
    __syncthreads();
    if (tid == 0) {
        float l0 = Wgb[0], l1 = Wgb[1], l2 = Wgb[2];
        #pragma unroll
        for (int w = 0; w < 8; ++w) { l0 += red[w][0]; l1 += red[w][1]; l2 += red[w][2]; }
        float mx = fmaxf(l0, fmaxf(l1, l2));
        float e0 = expf(l0 - mx), e1 = expf(l1 - mx), e2 = expf(l2 - mx);
        float inv = 1.0f / (e0 + e1 + e2);
        gsm[0] = e0 * inv; gsm[1] = e1 * inv; gsm[2] = e2 * inv;
    }
    __syncthreads();
    float g0 = gsm[0], g1 = gsm[1], g2 = gsm[2];

    __half* Ah = g_A + (size_t)m * K3;
    #pragma unroll
    for (int it = 0; it < 2; ++it) {
        int e = (tid + it * 256) * 4;
        uint2 o;
        __half2 h0 = __floats2half2_rn(g0 * xv[it].x, g0 * xv[it].y);
        __half2 h1 = __floats2half2_rn(g0 * xv[it].z, g0 * xv[it].w);
        o.x = *(uint32_t*)&h0; o.y = *(uint32_t*)&h1;
        *(uint2*)(Ah + e) = o;
        h0 = __floats2half2_rn(g1 * iv[it].x, g1 * iv[it].y);
        h1 = __floats2half2_rn(g1 * iv[it].z, g1 * iv[it].w);
        o.x = *(uint32_t*)&h0; o.y = *(uint32_t*)&h1;
        *(uint2*)(Ah + DD + e) = o;
        h0 = __floats2half2_rn(g2 * dv[it].x, g2 * dv[it].y);
        h1 = __floats2half2_rn(g2 * dv[it].z, g2 * dv[it].w);
        o.x = *(uint32_t*)&h0; o.y = *(uint32_t*)&h1;
        *(uint2*)(Ah + 2 * DD + e) = o;
    }
}

// ---------------------------------------------------------------------------
// Kernel 4: mma.sync fp16 GEMM:  y = A * W^T + bias
// Block 128x128, BK=64 (96 K-steps, half the barriers of BK=32).
// 256 threads = 8 warps (4m x 2n), warp 32x64.
// 3-stage cp.async pipeline (36KB/stage = 108KB), 2 CTAs/SM.
// Register double-buffered fragments across the 4 k16 subticks.
// ROWSTRIDE 144B: stride mod 128 = 16B -> conflict-free ldmatrix phases.
// ---------------------------------------------------------------------------
#define NKSTEP 96               // K3 / 64
#define ROWSTRIDE 144
#define A_OFF 0
#define B_OFF (128 * ROWSTRIDE)            // 18432
#define STAGE_BYTES (2 * 128 * ROWSTRIDE)  // 36864
#define NSTAGE 3
#define GEMM_SMEM (NSTAGE * STAGE_BYTES)   // 110592

__device__ __forceinline__ void issue_stage(uint32_t sbase, int kstep, int slot,
                                            int m0, int n0, int tid) {
    const int k0 = kstep * 64;
    uint32_t sS = sbase + slot * STAGE_BYTES;

    // A tile: 128 rows x 8 chunks of 16B (128B/row) -> 1024 ops, 4/thread
    #pragma unroll
    for (int q = 0; q < 4; ++q) {
        int idx = tid + q * 256;
        int row = idx >> 3, c = idx & 7;
        size_t go = (((size_t)(m0 + row) * K3 + k0) << 1) + c * 16;
        cp16(sS + A_OFF + row * ROWSTRIDE + c * 16, (const char*)g_A + go);
    }
    // B tile: same shape
    #pragma unroll
    for (int q = 0; q < 4; ++q) {
        int idx = tid + q * 256;
        int row = idx >> 3, c = idx & 7;
        size_t go = (((size_t)(n0 + row) * K3 + k0) << 1) + c * 16;
        cp16(sS + B_OFF + row * ROWSTRIDE + c * 16, (const char*)g_W + go);
    }
    CP_COMMIT();
}

__global__ __launch_bounds__(256, 2)
void gemm_kernel(const float* __restrict__ bias, float* __restrict__ y) {
    extern __shared__ char smem[];
    uint32_t sbase = smem_u32(smem);
    const int tid  = threadIdx.x;
    const int wid  = tid >> 5;
    const int lane = tid & 31;
    const int n0 = blockIdx.x * 128;
    const int m0 = blockIdx.y * 128;

    const int m_base = (wid & 3) * 32;    // 4 warps along m
    const int n_base = (wid >> 2) * 64;   // 2 warps along n

    // ldmatrix pattern: row = base + (lane&15), 16B chunk = lane>>4
    const uint32_t frag_off = (lane & 15) * ROWSTRIDE + (lane >> 4) * 16;

    float acc[2][8][4];
    #pragma unroll
    for (int i = 0; i < 2; ++i)
        #pragma unroll
        for (int j = 0; j < 8; ++j)
            #pragma unroll
            for (int q = 0; q < 4; ++q) acc[i][j][q] = 0.0f;

    // prologue: 2 stages ahead
    issue_stage(sbase, 0, 0, m0, n0, tid);
    issue_stage(sbase, 1, 1, m0, n0, tid);

    int slot = 0, slot2 = 2;    // slot = i%3, slot2 = (i+2)%3
    for (int i = 0; i < NKSTEP; ++i) {
        if (i + 2 < NKSTEP) CP_WAIT(1);
        else                CP_WAIT(0);   // exact tail drain
        __syncthreads();

        if (i + 2 < NKSTEP)
            issue_stage(sbase, i + 2, slot2, m0, n0, tid);

        uint32_t sS = sbase + slot * STAGE_BYTES;
        uint32_t aA = sS + A_OFF + m_base * ROWSTRIDE + frag_off;
        uint32_t aB = sS + B_OFF + n_base * ROWSTRIDE + frag_off;

        // 4 k16 subticks, register double-buffered (load kk+1 during mma kk)
        uint32_t a[2][2][4], b[2][4][4];
        #pragma unroll
        for (int mt = 0; mt < 2; ++mt) ldm_x4(a[0][mt], aA + mt * (16 * ROWSTRIDE));
        #pragma unroll
        for (int nt = 0; nt < 4; ++nt) ldm_x4(b[0][nt], aB + nt * (16 * ROWSTRIDE));

        #pragma unroll
        for (int kk = 0; kk < 4; ++kk) {
            int cur = kk & 1, nxt = cur ^ 1;
            if (kk < 3) {
                #pragma unroll
                for (int mt = 0; mt < 2; ++mt)
                    ldm_x4(a[nxt][mt], aA + mt * (16 * ROWSTRIDE) + (kk + 1) * 32);
                #pragma unroll
                for (int nt = 0; nt < 4; ++nt)
                    ldm_x4(b[nxt][nt], aB + nt * (16 * ROWSTRIDE) + (kk + 1) * 32);
            }
            // non-trans ldmatrix on n-major B: {r0,r2} = n0-7, {r1,r3} = n8-15
            #pragma unroll
            for (int mt = 0; mt < 2; ++mt)
                #pragma unroll
                for (int nt = 0; nt < 4; ++nt) {
                    mma_f16(acc[mt][2 * nt + 0], a[cur][mt], b[cur][nt][0], b[cur][nt][2]);
                    mma_f16(acc[mt][2 * nt + 1], a[cur][mt], b[cur][nt][1], b[cur][nt][3]);
                }
        }

        slot  = (slot  + 1 == NSTAGE) ? 0 : slot  + 1;
        slot2 = (slot2 + 1 == NSTAGE) ? 0 : slot2 + 1;
    }

    // epilogue: c frag mapping -> y + bias
    const int g  = lane >> 2;
    const int tg = lane & 3;
    #pragma unroll
    for (int mt = 0; mt < 2; ++mt) {
        int m = m0 + m_base + mt * 16 + g;
        #pragma unroll
        for (int nt = 0; nt < 8; ++nt) {
            int n = n0 + n_base + nt * 8 + tg * 2;
            float b0 = bias[n], b1 = bias[n + 1];
            float2 v0 = make_float2(acc[mt][nt][0] + b0, acc[mt][nt][1] + b1);
            float2 v1 = make_float2(acc[mt][nt][2] + b0, acc[mt][nt][3] + b1);
            *(float2*)(y + (size_t)m * DD + n)       = v0;
            *(float2*)(y + (size_t)(m + 8) * DD + n) = v1;
        }
    }
}

// ---------------------------------------------------------------------------
// Launch
// ---------------------------------------------------------------------------
extern "C" void kernel_launch(void* const* d_in, const int* in_sizes, int n_in,
                              void* d_out, int out_size) {
    const float* x     = (const float*)d_in[0];
    const float* W_p   = (const float*)d_in[1];
    const float* W_i   = (const float*)d_in[2];
    const float* W_d   = (const float*)d_in[3];
    const float* a_log = (const float*)d_in[4];
    const float* b_log = (const float*)d_in[5];
    const float* W_gw  = (const float*)d_in[6];
    const float* W_gb  = (const float*)d_in[7];
    const float* bias  = (const float*)d_in[8];
    float* y = (float*)d_out;

    cudaFuncSetAttribute(gemm_kernel,
                         cudaFuncAttributeMaxDynamicSharedMemorySize, GEMM_SMEM);

    // 1) weight conversion
    {
        int n4 = DD * K3 / 4;
        wconv_kernel<<<(n4 + 255) / 256, 256>>>(W_p, W_i, W_d);
    }
    // 2) chunked temporal scan + carry fixup
    scan_local_kernel<<<(BB * DD * NCHUNK + 127) / 128, 128>>>(x, a_log, b_log);
    scan_fix_kernel<<<(BB * DD + 127) / 128, 128>>>(a_log, b_log);
    // 3) gates + fp16 feature emit
    gate_kernel<<<MTOT, 256>>>(x, W_gw, W_gb);
    // 4) tensor-core GEMM + bias, 2 CTAs/SM
    dim3 grid(DD / 128, MTOT / 128);   // (16, 64) = 1024 blocks
    gemm_kernel<<<grid, 256, GEMM_SMEM>>>(bias, y);
}